// round 1
// baseline (speedup 1.0000x reference)
#include <cuda_runtime.h>
#include <math.h>

#define BB 4
#define SS 512
#define EE 512
#define HH 8
#define HD 64
#define CC 128
#define NROW (BB*SS)          // 2048

// ---------------- scratch (static device globals; no allocation) ----------------
__device__ float g_q[BB*HH*SS*HD];     // 4 MB
__device__ float g_k[BB*HH*SS*HD];
__device__ float g_v[BB*HH*SS*HD];
__device__ float g_s[(size_t)BB*HH*SS*SS];   // 32 MB
__device__ float g_ma[BB*SS*SS];       // 4 MB
__device__ float g_tp[BB*SS*SS];       // 4 MB
__device__ float g_oh[BB*SS*EE];       // 4 MB
__device__ double g_acc[BB*5];         // sum_ma, sum_ma2, sum_H, sum_t, sum_t2
__device__ int    g_amax[BB];
__device__ float  g_coef[BB*3];

// ---------------- helpers ----------------
__device__ __forceinline__ float clipf(float v, float lo, float hi) {
    return fminf(fmaxf(v, lo), hi);
}

__device__ __forceinline__ float blockReduceSum(float v, float* red, int t) {
    red[t] = v; __syncthreads();
    #pragma unroll
    for (int o = 128; o > 0; o >>= 1) {
        if (t < o) red[t] += red[t + o];
        __syncthreads();
    }
    float r = red[0]; __syncthreads();
    return r;
}

__device__ __forceinline__ float blockReduceMax(float v, float* red, int t) {
    red[t] = v; __syncthreads();
    #pragma unroll
    for (int o = 128; o > 0; o >>= 1) {
        if (t < o) red[t] = fmaxf(red[t], red[t + o]);
        __syncthreads();
    }
    float r = red[0]; __syncthreads();
    return r;
}

// ---------------- K1/K7: generic projection GEMM  C = A[2048,512] @ W[512,512] + b ----------------
// headMode=1: write to [B,H,S,hd] layout; headMode=0: plain [M,N]
__global__ void gemm_proj(const float* __restrict__ A, const float* __restrict__ W,
                          const float* __restrict__ bias, float* __restrict__ out,
                          int headMode)
{
    __shared__ float As[64][17];
    __shared__ float Ws[16][65];
    int tx = threadIdx.x, ty = threadIdx.y;
    int t = ty * 16 + tx;
    int m0 = blockIdx.y * 64, n0 = blockIdx.x * 64;
    float acc[4][4] = {};

    for (int k0 = 0; k0 < EE; k0 += 16) {
        #pragma unroll
        for (int r = 0; r < 4; r++) {
            int e = t + r * 256;
            int row = e >> 4, kk = e & 15;
            As[row][kk] = A[(size_t)(m0 + row) * EE + k0 + kk];
        }
        #pragma unroll
        for (int r = 0; r < 4; r++) {
            int e = t + r * 256;
            int kk = e >> 6, n = e & 63;
            Ws[kk][n] = W[(size_t)(k0 + kk) * EE + n0 + n];
        }
        __syncthreads();
        #pragma unroll
        for (int kk = 0; kk < 16; kk++) {
            float a[4], bv[4];
            #pragma unroll
            for (int i = 0; i < 4; i++) a[i] = As[ty * 4 + i][kk];
            #pragma unroll
            for (int j = 0; j < 4; j++) bv[j] = Ws[kk][tx * 4 + j];
            #pragma unroll
            for (int i = 0; i < 4; i++)
                #pragma unroll
                for (int j = 0; j < 4; j++)
                    acc[i][j] += a[i] * bv[j];
        }
        __syncthreads();
    }

    #pragma unroll
    for (int i = 0; i < 4; i++) {
        int m = m0 + ty * 4 + i;
        #pragma unroll
        for (int j = 0; j < 4; j++) {
            int n = n0 + tx * 4 + j;
            float val = acc[i][j] + bias[n];
            if (headMode) {
                int b = m >> 9, si = m & 511;
                int h = n >> 6, d = n & 63;
                out[(((size_t)(b * HH + h) * SS) + si) * HD + d] = val;
            } else {
                out[(size_t)m * EE + n] = val;
            }
        }
    }
}

// ---------------- K2: batched S = Q K^T * scale, nan_to_num + clip[-15,15] ----------------
__global__ void qk_gemm(const float* __restrict__ q, const float* __restrict__ k,
                        float* __restrict__ s)
{
    __shared__ float Qs[64][65];
    __shared__ float Ks[64][65];
    int tx = threadIdx.x, ty = threadIdx.y;
    int t = ty * 16 + tx;
    int bh = blockIdx.z;
    int i0 = blockIdx.y * 64, j0 = blockIdx.x * 64;
    const float* qb = q + (size_t)bh * SS * HD;
    const float* kb = k + (size_t)bh * SS * HD;

    #pragma unroll
    for (int r = 0; r < 16; r++) {
        int e = t + r * 256;
        int row = e >> 6, d = e & 63;
        Qs[row][d] = qb[(size_t)(i0 + row) * HD + d];
        Ks[d][row] = kb[(size_t)(j0 + row) * HD + d];   // stored transposed: Ks[kk][col]
    }
    __syncthreads();

    float acc[4][4] = {};
    #pragma unroll 8
    for (int kk = 0; kk < 64; kk++) {
        float a[4], bv[4];
        #pragma unroll
        for (int i = 0; i < 4; i++) a[i] = Qs[ty * 4 + i][kk];
        #pragma unroll
        for (int j = 0; j < 4; j++) bv[j] = Ks[kk][tx * 4 + j];
        #pragma unroll
        for (int i = 0; i < 4; i++)
            #pragma unroll
            for (int j = 0; j < 4; j++)
                acc[i][j] += a[i] * bv[j];
    }

    const float scale = 0.125f;   // hd^-0.5 = 1/8
    float* srow = s + (size_t)bh * SS * SS;
    #pragma unroll
    for (int i = 0; i < 4; i++)
        #pragma unroll
        for (int j = 0; j < 4; j++) {
            float v = acc[i][j] * scale;
            if (isnan(v)) v = 0.f;
            else if (isinf(v)) v = v > 0.f ? 10.f : -10.f;
            v = clipf(v, -15.f, 15.f);
            srow[(size_t)(i0 + ty * 4 + i) * SS + j0 + tx * 4 + j] = v;
        }
}

// ---------------- K3: ma = mean over heads ----------------
__global__ void ma_kernel(const float* __restrict__ s, float* __restrict__ ma)
{
    int idx = blockIdx.x * blockDim.x + threadIdx.x;   // < B*S*S
    int b = idx >> 18;                                  // S*S = 2^18
    int r = idx & (SS * SS - 1);
    const float* base = s + (size_t)b * HH * SS * SS + r;
    float acc = 0.f;
    #pragma unroll
    for (int h = 0; h < HH; h++) acc += base[(size_t)h * SS * SS];
    ma[idx] = acc * 0.125f;
}

// ---------------- init accumulators ----------------
__global__ void init_acc()
{
    int t = threadIdx.x;
    if (t < BB * 5) g_acc[t] = 0.0;
    if (t < BB) g_amax[t] = 0;
}

// ---------------- K4: per-row transform, produces t_pre + per-batch partials ----------------
__global__ void row_transform(const float* __restrict__ ma, float* __restrict__ tp,
                              const float* __restrict__ w1, const float* __restrict__ b1,
                              const float* __restrict__ w2, const float* __restrict__ b2)
{
    __shared__ float red[256];
    __shared__ float w1s[CC], b1s[CC], w2s[CC];
    int t = threadIdx.x;
    int row = blockIdx.x;          // 0..2047
    int b = row >> 9;

    if (t < CC) { w1s[t] = w1[t]; b1s[t] = b1[t]; w2s[t] = w2[t]; }

    const float* mrow = ma + (size_t)row * SS;
    float m0 = mrow[t], m1 = mrow[t + 256];
    float c0 = clipf(m0, -10.f, 10.f), c1 = clipf(m1, -10.f, 10.f);
    __syncthreads();

    // p = softmax(clip(ma,-10,10))
    float mx = blockReduceMax(fmaxf(c0, c1), red, t);
    float e0 = expf(c0 - mx), e1 = expf(c1 - mx);
    float sum = blockReduceSum(e0 + e1, red, t);
    float inv = 1.f / sum;
    float p0 = e0 * inv, p1 = e1 * inv;
    float h0 = -p0 * logf(p0 + 1e-6f);
    float h1 = -p1 * logf(p1 + 1e-6f);

    // Fm = softmax(3 * Hent)
    float fmx = 3.f * blockReduceMax(fmaxf(h0, h1), red, t);
    float f0 = expf(3.f * h0 - fmx), f1 = expf(3.f * h1 - fmx);
    float fsum = blockReduceSum(f0 + f1, red, t);
    float finv = 1.f / fsum;
    float F0 = f0 * finv, F1 = f1 * finv;

    // ap MLP (128 channels) -> sig -> t_pre
    float b2v = b2[0];
    float sa0 = clipf(clipf(m0, -8.f, 8.f) * 0.05f, -10.f, 10.f);
    float sa1 = clipf(clipf(m1, -8.f, 8.f) * 0.05f, -10.f, 10.f);
    float a0 = 0.f, a1 = 0.f;
    #pragma unroll 8
    for (int c = 0; c < CC; c++) {
        float w = w1s[c], bb = b1s[c], w2v = w2s[c];
        // relu(clip(x,-5,5)) == min(max(x,0),5)
        float hh0 = fminf(fmaxf(sa0 * w + bb, 0.f), 5.f);
        float hh1 = fminf(fmaxf(sa1 * w + bb, 0.f), 5.f);
        a0 += hh0 * w2v;
        a1 += hh1 * w2v;
    }
    float ap0 = clipf(a0 + b2v, -5.f, 5.f);
    float ap1 = clipf(a1 + b2v, -5.f, 5.f);
    float ty0 = clipf(1.f + 0.05f * (ap0 * 50.f), 0.5f, 1.5f);
    float ty1 = clipf(1.f + 0.05f * (ap1 * 50.f), 0.5f, 1.5f);
    float sg0 = 1.f / (1.f + expf(-ty0));
    float sg1 = 1.f / (1.f + expf(-ty1));
    float tp0 = sg0 * F0, tp1 = sg1 * F1;

    tp[(size_t)row * SS + t]       = tp0;
    tp[(size_t)row * SS + t + 256] = tp1;

    // per-batch partials
    float sma  = blockReduceSum(m0 + m1, red, t);
    float sma2 = blockReduceSum(m0 * m0 + m1 * m1, red, t);
    float shh  = blockReduceSum(h0 + h1, red, t);
    float stt  = blockReduceSum(tp0 + tp1, red, t);
    float st2  = blockReduceSum(tp0 * tp0 + tp1 * tp1, red, t);
    float amx  = blockReduceMax(fmaxf(fabsf(m0), fabsf(m1)), red, t);

    if (t == 0) {
        atomicAdd(&g_acc[b * 5 + 0], (double)sma);
        atomicAdd(&g_acc[b * 5 + 1], (double)sma2);
        atomicAdd(&g_acc[b * 5 + 2], (double)shh);
        atomicAdd(&g_acc[b * 5 + 3], (double)stt);
        atomicAdd(&g_acc[b * 5 + 4], (double)st2);
        atomicMax(&g_amax[b], __float_as_int(amx));   // non-negative floats: int order OK
    }
}

// ---------------- K5: finalize per-batch coefficients ----------------
// delta[b,i,j] = A + B * t_pre - rr * ma   with
//   A = rr*tm*(1-sm*gd), B = rr*sm*gd*c, Cc = rr
__global__ void finalize_kernel()
{
    int b = threadIdx.x;
    if (b < BB) {
        const double N = (double)SS * (double)SS;
        double sma  = g_acc[b * 5 + 0];
        double sma2 = g_acc[b * 5 + 1];
        double sh   = g_acc[b * 5 + 2];
        double st   = g_acc[b * 5 + 3];
        double st2  = g_acc[b * 5 + 4];
        float amaxv = __int_as_float(g_amax[b]);

        float eo = sqrtf((float)sma2) + 1e-4f;
        float et = sqrtf((float)st2) + 1e-4f;
        float c  = clipf(eo / et, 0.8f, 1.2f);
        float tm = c * (float)(st / N);
        float tvar = c * c * (float)(st2 / N - (st / N) * (st / N));
        tvar = fmaxf(tvar, 0.01f);
        float ovar = (float)(sma2 / N - (sma / N) * (sma / N));
        ovar = fmaxf(ovar, 0.01f);
        float gd = clipf(sqrtf(ovar) / sqrtf(tvar), 0.8f, 1.2f);
        float ar = clipf(amaxv, 1.f, 10.f);
        float sm = clipf(0.3f / log1pf(ar), 0.1f, 0.5f);
        float ent = (float)(sh / N);
        float ne = ent / logf((float)SS);
        float rr = 0.4f * (1.f - clipf(ne, 0.f, 0.4f));
        float smgd = sm * gd;

        g_coef[b * 3 + 0] = rr * tm * (1.f - smgd);
        g_coef[b * 3 + 1] = rr * smgd * c;
        g_coef[b * 3 + 2] = rr;
    }
}

// ---------------- K6a: per-(b,h,row) delta-add + softmax(s/tau), in place ----------------
__global__ void attn_softmax(float* __restrict__ s, const float* __restrict__ ma,
                             const float* __restrict__ tp, const float* __restrict__ tau)
{
    __shared__ float red[256];
    int t = threadIdx.x;
    int idx = blockIdx.x;           // (b*H + h)*S + i
    int i  = idx & (SS - 1);
    int bh = idx >> 9;
    int b  = bh >> 3;

    float* srow = s + (size_t)idx * SS;
    const float* marow = ma + ((size_t)b * SS + i) * SS;
    const float* trow  = tp + ((size_t)b * SS + i) * SS;
    float A  = g_coef[b * 3 + 0];
    float Bc = g_coef[b * 3 + 1];
    float Cc = g_coef[b * 3 + 2];
    float tauv = tau[0];

    float v0 = (srow[t]       + A + Bc * trow[t]       - Cc * marow[t])       / tauv;
    float v1 = (srow[t + 256] + A + Bc * trow[t + 256] - Cc * marow[t + 256]) / tauv;

    float mx = blockReduceMax(fmaxf(v0, v1), red, t);
    float e0 = expf(v0 - mx), e1 = expf(v1 - mx);
    float sum = blockReduceSum(e0 + e1, red, t);
    float inv = 1.f / sum;
    srow[t]       = e0 * inv;
    srow[t + 256] = e1 * inv;
}

// ---------------- K6b: batched attn @ V, write head-unpermuted [B,S,E] ----------------
__global__ void av_gemm(const float* __restrict__ attn, const float* __restrict__ v,
                        float* __restrict__ oh)
{
    __shared__ float As[64][17];
    __shared__ float Bs[16][65];
    int tx = threadIdx.x, ty = threadIdx.y;
    int t = ty * 16 + tx;
    int bh = blockIdx.z;
    int b = bh >> 3, h = bh & 7;
    int i0 = blockIdx.y * 64;
    const float* ab = attn + (size_t)bh * SS * SS;
    const float* vb = v + (size_t)bh * SS * HD;
    float acc[4][4] = {};

    for (int k0 = 0; k0 < SS; k0 += 16) {
        #pragma unroll
        for (int r = 0; r < 4; r++) {
            int e = t + r * 256;
            int row = e >> 4, kk = e & 15;
            As[row][kk] = ab[(size_t)(i0 + row) * SS + k0 + kk];
        }
        {
            int e = t + 0 * 256;
            int kk = e >> 6, d = e & 63;
            Bs[kk][d]     = vb[(size_t)(k0 + kk) * HD + d];
            e = t + 256;
            kk = e >> 6; d = e & 63;
            Bs[kk][d]     = vb[(size_t)(k0 + kk) * HD + d];
            e = t + 512;
            kk = e >> 6; d = e & 63;
            Bs[kk][d]     = vb[(size_t)(k0 + kk) * HD + d];
            e = t + 768;
            kk = e >> 6; d = e & 63;
            Bs[kk][d]     = vb[(size_t)(k0 + kk) * HD + d];
        }
        __syncthreads();
        #pragma unroll
        for (int kk = 0; kk < 16; kk++) {
            float a[4], bv[4];
            #pragma unroll
            for (int i = 0; i < 4; i++) a[i] = As[ty * 4 + i][kk];
            #pragma unroll
            for (int j = 0; j < 4; j++) bv[j] = Bs[kk][tx * 4 + j];
            #pragma unroll
            for (int i = 0; i < 4; i++)
                #pragma unroll
                for (int j = 0; j < 4; j++)
                    acc[i][j] += a[i] * bv[j];
        }
        __syncthreads();
    }

    #pragma unroll
    for (int i = 0; i < 4; i++) {
        int si = i0 + ty * 4 + i;
        #pragma unroll
        for (int j = 0; j < 4; j++) {
            int d = tx * 4 + j;
            oh[((size_t)b * SS + si) * EE + h * HD + d] = acc[i][j];
        }
    }
}

// ---------------- launch ----------------
extern "C" void kernel_launch(void* const* d_in, const int* in_sizes, int n_in,
                              void* d_out, int out_size)
{
    const float* x  = (const float*)d_in[0];
    const float* Wq = (const float*)d_in[1];
    const float* bq = (const float*)d_in[2];
    const float* Wk = (const float*)d_in[3];
    const float* bk = (const float*)d_in[4];
    const float* Wv = (const float*)d_in[5];
    const float* bv = (const float*)d_in[6];
    const float* Wo = (const float*)d_in[7];
    const float* bo = (const float*)d_in[8];
    const float* w1 = (const float*)d_in[9];
    const float* b1 = (const float*)d_in[10];
    const float* w2 = (const float*)d_in[11];
    const float* b2 = (const float*)d_in[12];
    const float* tau = (const float*)d_in[13];
    float* out = (float*)d_out;

    float *pq, *pk, *pv, *ps, *pma, *ptp, *poh;
    cudaGetSymbolAddress((void**)&pq, g_q);
    cudaGetSymbolAddress((void**)&pk, g_k);
    cudaGetSymbolAddress((void**)&pv, g_v);
    cudaGetSymbolAddress((void**)&ps, g_s);
    cudaGetSymbolAddress((void**)&pma, g_ma);
    cudaGetSymbolAddress((void**)&ptp, g_tp);
    cudaGetSymbolAddress((void**)&poh, g_oh);

    dim3 blk(16, 16);

    gemm_proj<<<dim3(8, 32), blk>>>(x, Wq, bq, pq, 1);
    gemm_proj<<<dim3(8, 32), blk>>>(x, Wk, bk, pk, 1);
    gemm_proj<<<dim3(8, 32), blk>>>(x, Wv, bv, pv, 1);

    qk_gemm<<<dim3(8, 8, BB * HH), blk>>>(pq, pk, ps);

    ma_kernel<<<(BB * SS * SS) / 256, 256>>>(ps, pma);

    init_acc<<<1, 32>>>();
    row_transform<<<NROW, 256>>>(pma, ptp, w1, b1, w2, b2);
    finalize_kernel<<<1, 32>>>();

    attn_softmax<<<BB * HH * SS, 256>>>(ps, pma, ptp, tau);

    av_gemm<<<dim3(1, 8, BB * HH), blk>>>(ps, pv, poh);

    gemm_proj<<<dim3(8, 32), blk>>>(poh, Wo, bo, out, 0);
}

// round 5
// speedup vs baseline: 1.4221x; 1.4221x over previous
#include <cuda_runtime.h>
#include <cuda_bf16.h>
#include <math.h>
#include <stdint.h>

#define BB 4
#define SS 512
#define EE 512
#define HH 8
#define HD 64
#define CC 128
#define NROW (BB*SS)          // 2048
#define PSTR 40               // smem row stride in bf16 (80B) -> conflict-free ldmatrix

// ---------------- scratch (static device globals; no allocation) ----------------
__device__ __nv_bfloat16 g_xhi[NROW*EE], g_xlo[NROW*EE];
__device__ __nv_bfloat16 g_wthi[4*EE*EE], g_wtlo[4*EE*EE];           // transposed [n][k]
__device__ __nv_bfloat16 g_qhi[BB*HH*SS*HD], g_qlo[BB*HH*SS*HD];     // [bh][s][d]
__device__ __nv_bfloat16 g_khi[BB*HH*SS*HD], g_klo[BB*HH*SS*HD];     // [bh][s][d]
__device__ __nv_bfloat16 g_vthi[BB*HH*HD*SS], g_vtlo[BB*HH*HD*SS];   // [bh][d][s]
__device__ float g_s[(size_t)BB*HH*SS*SS];                           // 32MB
__device__ float g_ma[BB*SS*SS];
__device__ float g_tp[BB*SS*SS];
__device__ __nv_bfloat16 g_ahi[(size_t)BB*HH*SS*SS], g_alo[(size_t)BB*HH*SS*SS];
__device__ __nv_bfloat16 g_ohhi[NROW*EE], g_ohlo[NROW*EE];           // [B,S,E]
__device__ double g_acc[BB*5];
__device__ int    g_amax[BB];
__device__ float  g_coef[BB*3];

// ---------------- helpers ----------------
__device__ __forceinline__ float clipf(float v, float lo, float hi) {
    return fminf(fmaxf(v, lo), hi);
}

__device__ __forceinline__ uint32_t smem_u32(const void* p) {
    uint32_t a;
    asm("{ .reg .u64 t; cvta.to.shared.u64 t, %1; cvt.u32.u64 %0, t; }" : "=r"(a) : "l"(p));
    return a;
}

__device__ __forceinline__ void ldsm4(uint32_t* a, uint32_t addr) {
    asm volatile("ldmatrix.sync.aligned.m8n8.x4.shared.b16 {%0,%1,%2,%3}, [%4];"
        : "=r"(a[0]), "=r"(a[1]), "=r"(a[2]), "=r"(a[3]) : "r"(addr));
}
__device__ __forceinline__ void ldsm2(uint32_t* a, uint32_t addr) {
    asm volatile("ldmatrix.sync.aligned.m8n8.x2.shared.b16 {%0,%1}, [%2];"
        : "=r"(a[0]), "=r"(a[1]) : "r"(addr));
}
__device__ __forceinline__ void mma_bf16(float* d, const uint32_t* a, const uint32_t* b) {
    asm volatile("mma.sync.aligned.m16n8k16.row.col.f32.bf16.bf16.f32 "
        "{%0,%1,%2,%3}, {%4,%5,%6,%7}, {%8,%9}, {%0,%1,%2,%3};"
        : "+f"(d[0]), "+f"(d[1]), "+f"(d[2]), "+f"(d[3])
        : "r"(a[0]), "r"(a[1]), "r"(a[2]), "r"(a[3]), "r"(b[0]), "r"(b[1]));
}

// ================= conversion kernels =================
__global__ void conv_split(const float* __restrict__ in, __nv_bfloat16* __restrict__ hi,
                           __nv_bfloat16* __restrict__ lo, int n)
{
    int i = blockIdx.x * 256 + threadIdx.x;
    if (i < n) {
        float v = in[i];
        __nv_bfloat16 h = __float2bfloat16_rn(v);
        hi[i] = h;
        lo[i] = __float2bfloat16_rn(v - __bfloat162float(h));
    }
}

// transpose + split: wt[n][k] = W[k][n]
__global__ void conv_w(const float* __restrict__ W, __nv_bfloat16* __restrict__ thi,
                       __nv_bfloat16* __restrict__ tlo)
{
    __shared__ float tile[32][33];
    int bx = blockIdx.x * 32, by = blockIdx.y * 32;
    int x = threadIdx.x, y = threadIdx.y;
    #pragma unroll
    for (int j = 0; j < 4; j++)
        tile[y + j * 8][x] = W[(size_t)(by + y + j * 8) * EE + bx + x];
    __syncthreads();
    #pragma unroll
    for (int j = 0; j < 4; j++) {
        float v = tile[x][y + j * 8];
        __nv_bfloat16 h = __float2bfloat16_rn(v);
        size_t dst = (size_t)(bx + y + j * 8) * EE + by + x;
        thi[dst] = h;
        tlo[dst] = __float2bfloat16_rn(v - __bfloat162float(h));
    }
}

// ================= fused QKV projection (mma.sync bf16 3-pass) =================
// grid (4, 16, 3): z=0 -> q [bh][s][d], z=1 -> k [bh][s][d], z=2 -> v transposed [bh][d][s]
__global__ void __launch_bounds__(256) proj_qkv(
    const __nv_bfloat16* __restrict__ xhi, const __nv_bfloat16* __restrict__ xlo,
    const __nv_bfloat16* __restrict__ wthi, const __nv_bfloat16* __restrict__ wtlo,
    const float* __restrict__ bq, const float* __restrict__ bk, const float* __restrict__ bv,
    __nv_bfloat16* __restrict__ qhi, __nv_bfloat16* __restrict__ qlo,
    __nv_bfloat16* __restrict__ khi, __nv_bfloat16* __restrict__ klo,
    __nv_bfloat16* __restrict__ vthi, __nv_bfloat16* __restrict__ vtlo)
{
    __shared__ __nv_bfloat16 sAh[128*PSTR], sAl[128*PSTR], sBh[128*PSTR], sBl[128*PSTR];
    int t = threadIdx.x, lane = t & 31, wid = t >> 5;
    int wm = wid >> 2, wn = wid & 3;
    int z = blockIdx.z;
    int n0 = blockIdx.x * 128, m0 = blockIdx.y * 128;
    const __nv_bfloat16* Bh = wthi + (size_t)z * EE * EE;
    const __nv_bfloat16* Bl = wtlo + (size_t)z * EE * EE;
    const float* bias = (z == 0) ? bq : ((z == 1) ? bk : bv);

    uint32_t bAh = smem_u32(sAh), bAl = smem_u32(sAl), bBh = smem_u32(sBh), bBl = smem_u32(sBl);
    float acc[4][4][4] = {};

    int mat = lane >> 3, r8 = lane & 7;

    for (int kc = 0; kc < 16; kc++) {
        #pragma unroll
        for (int i = t; i < 512; i += 256) {
            int row = i >> 2, seg = i & 3;
            size_t ga = (size_t)(m0 + row) * EE + kc * 32 + seg * 8;
            *(uint4*)&sAh[row * PSTR + seg * 8] = *(const uint4*)&xhi[ga];
            *(uint4*)&sAl[row * PSTR + seg * 8] = *(const uint4*)&xlo[ga];
            size_t gb = (size_t)(n0 + row) * EE + kc * 32 + seg * 8;
            *(uint4*)&sBh[row * PSTR + seg * 8] = *(const uint4*)&Bh[gb];
            *(uint4*)&sBl[row * PSTR + seg * 8] = *(const uint4*)&Bl[gb];
        }
        __syncthreads();
        #pragma unroll
        for (int kk = 0; kk < 2; kk++) {
            uint32_t ah[4][4], al[4][4], bhf[4][2], blf[4][2];
            uint32_t aoff = (uint32_t)((wm * 64 + r8 + (mat & 1) * 8) * PSTR + kk * 16 + (mat >> 1) * 8) * 2;
            #pragma unroll
            for (int fm = 0; fm < 4; fm++) {
                uint32_t o = aoff + fm * 16 * PSTR * 2;
                ldsm4(ah[fm], bAh + o);
                ldsm4(al[fm], bAl + o);
            }
            uint32_t boff = (uint32_t)((wn * 32 + r8) * PSTR + kk * 16 + (mat & 1) * 8) * 2;
            #pragma unroll
            for (int fn = 0; fn < 4; fn++) {
                uint32_t o = boff + fn * 8 * PSTR * 2;
                ldsm2(bhf[fn], bBh + o);
                ldsm2(blf[fn], bBl + o);
            }
            #pragma unroll
            for (int fm = 0; fm < 4; fm++)
                #pragma unroll
                for (int fn = 0; fn < 4; fn++) {
                    mma_bf16(acc[fm][fn], ah[fm], bhf[fn]);
                    mma_bf16(acc[fm][fn], ah[fm], blf[fn]);
                    mma_bf16(acc[fm][fn], al[fm], bhf[fn]);
                }
        }
        __syncthreads();
    }

    #pragma unroll
    for (int fm = 0; fm < 4; fm++)
        #pragma unroll
        for (int fn = 0; fn < 4; fn++)
            #pragma unroll
            for (int dr = 0; dr < 4; dr++) {
                int m = m0 + wm * 64 + fm * 16 + (lane >> 2) + (dr >> 1) * 8;
                int n = n0 + wn * 32 + fn * 8 + (lane & 3) * 2 + (dr & 1);
                float v = acc[fm][fn][dr] + bias[n];
                int b = m >> 9, s = m & 511;
                int h = n >> 6, d = n & 63;
                __nv_bfloat16 hh = __float2bfloat16_rn(v);
                __nv_bfloat16 ll = __float2bfloat16_rn(v - __bfloat162float(hh));
                if (z == 0) {
                    size_t dst = (((size_t)(b * HH + h) * SS) + s) * HD + d;
                    qhi[dst] = hh; qlo[dst] = ll;
                } else if (z == 1) {
                    size_t dst = (((size_t)(b * HH + h) * SS) + s) * HD + d;
                    khi[dst] = hh; klo[dst] = ll;
                } else {
                    size_t dst = (((size_t)(b * HH + h) * HD) + d) * SS + s;
                    vthi[dst] = hh; vtlo[dst] = ll;
                }
            }
}

// ================= output projection: fp32 result =================
__global__ void __launch_bounds__(256) proj_out(
    const __nv_bfloat16* __restrict__ ahi, const __nv_bfloat16* __restrict__ alo,
    const __nv_bfloat16* __restrict__ wthi, const __nv_bfloat16* __restrict__ wtlo,
    const float* __restrict__ bias, float* __restrict__ out)
{
    __shared__ __nv_bfloat16 sAh[128*PSTR], sAl[128*PSTR], sBh[128*PSTR], sBl[128*PSTR];
    int t = threadIdx.x, lane = t & 31, wid = t >> 5;
    int wm = wid >> 2, wn = wid & 3;
    int n0 = blockIdx.x * 128, m0 = blockIdx.y * 128;
    const __nv_bfloat16* Bh = wthi + (size_t)3 * EE * EE;
    const __nv_bfloat16* Bl = wtlo + (size_t)3 * EE * EE;

    uint32_t bAh = smem_u32(sAh), bAl = smem_u32(sAl), bBh = smem_u32(sBh), bBl = smem_u32(sBl);
    float acc[4][4][4] = {};
    int mat = lane >> 3, r8 = lane & 7;

    for (int kc = 0; kc < 16; kc++) {
        #pragma unroll
        for (int i = t; i < 512; i += 256) {
            int row = i >> 2, seg = i & 3;
            size_t ga = (size_t)(m0 + row) * EE + kc * 32 + seg * 8;
            *(uint4*)&sAh[row * PSTR + seg * 8] = *(const uint4*)&ahi[ga];
            *(uint4*)&sAl[row * PSTR + seg * 8] = *(const uint4*)&alo[ga];
            size_t gb = (size_t)(n0 + row) * EE + kc * 32 + seg * 8;
            *(uint4*)&sBh[row * PSTR + seg * 8] = *(const uint4*)&Bh[gb];
            *(uint4*)&sBl[row * PSTR + seg * 8] = *(const uint4*)&Bl[gb];
        }
        __syncthreads();
        #pragma unroll
        for (int kk = 0; kk < 2; kk++) {
            uint32_t ah[4][4], al[4][4], bhf[4][2], blf[4][2];
            uint32_t aoff = (uint32_t)((wm * 64 + r8 + (mat & 1) * 8) * PSTR + kk * 16 + (mat >> 1) * 8) * 2;
            #pragma unroll
            for (int fm = 0; fm < 4; fm++) {
                uint32_t o = aoff + fm * 16 * PSTR * 2;
                ldsm4(ah[fm], bAh + o);
                ldsm4(al[fm], bAl + o);
            }
            uint32_t boff = (uint32_t)((wn * 32 + r8) * PSTR + kk * 16 + (mat & 1) * 8) * 2;
            #pragma unroll
            for (int fn = 0; fn < 4; fn++) {
                uint32_t o = boff + fn * 8 * PSTR * 2;
                ldsm2(bhf[fn], bBh + o);
                ldsm2(blf[fn], bBl + o);
            }
            #pragma unroll
            for (int fm = 0; fm < 4; fm++)
                #pragma unroll
                for (int fn = 0; fn < 4; fn++) {
                    mma_bf16(acc[fm][fn], ah[fm], bhf[fn]);
                    mma_bf16(acc[fm][fn], ah[fm], blf[fn]);
                    mma_bf16(acc[fm][fn], al[fm], bhf[fn]);
                }
        }
        __syncthreads();
    }

    #pragma unroll
    for (int fm = 0; fm < 4; fm++)
        #pragma unroll
        for (int fn = 0; fn < 4; fn++)
            #pragma unroll
            for (int dr = 0; dr < 4; dr++) {
                int m = m0 + wm * 64 + fm * 16 + (lane >> 2) + (dr >> 1) * 8;
                int n = n0 + wn * 32 + fn * 8 + (lane & 3) * 2 + (dr & 1);
                out[(size_t)m * EE + n] = acc[fm][fn][dr] + bias[n];
            }
}

// ================= batched QK^T: scale + nan + clip =================
// grid (4 j, 4 i, 32 bh)
__global__ void __launch_bounds__(256) qk_mma(
    const __nv_bfloat16* __restrict__ qhi, const __nv_bfloat16* __restrict__ qlo,
    const __nv_bfloat16* __restrict__ khi, const __nv_bfloat16* __restrict__ klo,
    float* __restrict__ s)
{
    __shared__ __nv_bfloat16 sAh[128*PSTR], sAl[128*PSTR], sBh[128*PSTR], sBl[128*PSTR];
    int t = threadIdx.x, lane = t & 31, wid = t >> 5;
    int wm = wid >> 2, wn = wid & 3;
    int j0 = blockIdx.x * 128, i0 = blockIdx.y * 128, bh = blockIdx.z;

    uint32_t bAh = smem_u32(sAh), bAl = smem_u32(sAl), bBh = smem_u32(sBh), bBl = smem_u32(sBl);
    float acc[4][4][4] = {};
    int mat = lane >> 3, r8 = lane & 7;

    for (int kc = 0; kc < 2; kc++) {
        #pragma unroll
        for (int i = t; i < 512; i += 256) {
            int row = i >> 2, seg = i & 3;
            size_t ga = ((size_t)bh * SS + i0 + row) * HD + kc * 32 + seg * 8;
            *(uint4*)&sAh[row * PSTR + seg * 8] = *(const uint4*)&qhi[ga];
            *(uint4*)&sAl[row * PSTR + seg * 8] = *(const uint4*)&qlo[ga];
            size_t gb = ((size_t)bh * SS + j0 + row) * HD + kc * 32 + seg * 8;
            *(uint4*)&sBh[row * PSTR + seg * 8] = *(const uint4*)&khi[gb];
            *(uint4*)&sBl[row * PSTR + seg * 8] = *(const uint4*)&klo[gb];
        }
        __syncthreads();
        #pragma unroll
        for (int kk = 0; kk < 2; kk++) {
            uint32_t ah[4][4], al[4][4], bhf[4][2], blf[4][2];
            uint32_t aoff = (uint32_t)((wm * 64 + r8 + (mat & 1) * 8) * PSTR + kk * 16 + (mat >> 1) * 8) * 2;
            #pragma unroll
            for (int fm = 0; fm < 4; fm++) {
                uint32_t o = aoff + fm * 16 * PSTR * 2;
                ldsm4(ah[fm], bAh + o);
                ldsm4(al[fm], bAl + o);
            }
            uint32_t boff = (uint32_t)((wn * 32 + r8) * PSTR + kk * 16 + (mat & 1) * 8) * 2;
            #pragma unroll
            for (int fn = 0; fn < 4; fn++) {
                uint32_t o = boff + fn * 8 * PSTR * 2;
                ldsm2(bhf[fn], bBh + o);
                ldsm2(blf[fn], bBl + o);
            }
            #pragma unroll
            for (int fm = 0; fm < 4; fm++)
                #pragma unroll
                for (int fn = 0; fn < 4; fn++) {
                    mma_bf16(acc[fm][fn], ah[fm], bhf[fn]);
                    mma_bf16(acc[fm][fn], ah[fm], blf[fn]);
                    mma_bf16(acc[fm][fn], al[fm], bhf[fn]);
                }
        }
        __syncthreads();
    }

    float* sbase = s + (size_t)bh * SS * SS;
    #pragma unroll
    for (int fm = 0; fm < 4; fm++)
        #pragma unroll
        for (int fn = 0; fn < 4; fn++)
            #pragma unroll
            for (int dr = 0; dr < 4; dr++) {
                int mi = i0 + wm * 64 + fm * 16 + (lane >> 2) + (dr >> 1) * 8;
                int nj = j0 + wn * 32 + fn * 8 + (lane & 3) * 2 + (dr & 1);
                float v = acc[fm][fn][dr] * 0.125f;
                if (isnan(v)) v = 0.f;
                else if (isinf(v)) v = v > 0.f ? 10.f : -10.f;
                v = clipf(v, -15.f, 15.f);
                sbase[(size_t)mi * SS + nj] = v;
            }
}

// ================= batched attn @ V -> oh [B,S,E] hi/lo =================
// grid (4 i, 32 bh); N=64
__global__ void __launch_bounds__(256) av_mma(
    const __nv_bfloat16* __restrict__ ahi, const __nv_bfloat16* __restrict__ alo,
    const __nv_bfloat16* __restrict__ vthi, const __nv_bfloat16* __restrict__ vtlo,
    __nv_bfloat16* __restrict__ ohi, __nv_bfloat16* __restrict__ olo)
{
    __shared__ __nv_bfloat16 sAh[128*PSTR], sAl[128*PSTR], sBh[64*PSTR], sBl[64*PSTR];
    int t = threadIdx.x, lane = t & 31, wid = t >> 5;
    int wm = wid >> 2, wn = wid & 3;
    int i0 = blockIdx.x * 128, bh = blockIdx.y;
    int b = bh >> 3, h = bh & 7;

    uint32_t bAh = smem_u32(sAh), bAl = smem_u32(sAl), bBh = smem_u32(sBh), bBl = smem_u32(sBl);
    float acc[4][2][4] = {};
    int mat = lane >> 3, r8 = lane & 7;

    for (int kc = 0; kc < 16; kc++) {
        #pragma unroll
        for (int i = t; i < 512; i += 256) {
            int row = i >> 2, seg = i & 3;
            size_t ga = (size_t)bh * SS * SS + (size_t)(i0 + row) * SS + kc * 32 + seg * 8;
            *(uint4*)&sAh[row * PSTR + seg * 8] = *(const uint4*)&ahi[ga];
            *(uint4*)&sAl[row * PSTR + seg * 8] = *(const uint4*)&alo[ga];
        }
        {
            int row = t >> 2, seg = t & 3;   // 64 rows x 4 segs = 256
            size_t gb = ((size_t)bh * HD + row) * SS + kc * 32 + seg * 8;
            *(uint4*)&sBh[row * PSTR + seg * 8] = *(const uint4*)&vthi[gb];
            *(uint4*)&sBl[row * PSTR + seg * 8] = *(const uint4*)&vtlo[gb];
        }
        __syncthreads();
        #pragma unroll
        for (int kk = 0; kk < 2; kk++) {
            uint32_t ah[4][4], al[4][4], bhf[2][2], blf[2][2];
            uint32_t aoff = (uint32_t)((wm * 64 + r8 + (mat & 1) * 8) * PSTR + kk * 16 + (mat >> 1) * 8) * 2;
            #pragma unroll
            for (int fm = 0; fm < 4; fm++) {
                uint32_t o = aoff + fm * 16 * PSTR * 2;
                ldsm4(ah[fm], bAh + o);
                ldsm4(al[fm], bAl + o);
            }
            uint32_t boff = (uint32_t)((wn * 16 + r8) * PSTR + kk * 16 + (mat & 1) * 8) * 2;
            #pragma unroll
            for (int fn = 0; fn < 2; fn++) {
                uint32_t o = boff + fn * 8 * PSTR * 2;
                ldsm2(bhf[fn], bBh + o);
                ldsm2(blf[fn], bBl + o);
            }
            #pragma unroll
            for (int fm = 0; fm < 4; fm++)
                #pragma unroll
                for (int fn = 0; fn < 2; fn++) {
                    mma_bf16(acc[fm][fn], ah[fm], bhf[fn]);
                    mma_bf16(acc[fm][fn], ah[fm], blf[fn]);
                    mma_bf16(acc[fm][fn], al[fm], bhf[fn]);
                }
        }
        __syncthreads();
    }

    #pragma unroll
    for (int fm = 0; fm < 4; fm++)
        #pragma unroll
        for (int fn = 0; fn < 2; fn++)
            #pragma unroll
            for (int dr = 0; dr < 4; dr++) {
                int si = i0 + wm * 64 + fm * 16 + (lane >> 2) + (dr >> 1) * 8;
                int d  = wn * 16 + fn * 8 + (lane & 3) * 2 + (dr & 1);
                float v = acc[fm][fn][dr];
                size_t dst = ((size_t)b * SS + si) * EE + h * HD + d;
                __nv_bfloat16 hh = __float2bfloat16_rn(v);
                ohi[dst] = hh;
                olo[dst] = __float2bfloat16_rn(v - __bfloat162float(hh));
            }
}

// ================= elementwise stages (from R1, verified) =================
__device__ __forceinline__ float blockReduceSum(float v, float* red, int t) {
    red[t] = v; __syncthreads();
    #pragma unroll
    for (int o = 128; o > 0; o >>= 1) {
        if (t < o) red[t] += red[t + o];
        __syncthreads();
    }
    float r = red[0]; __syncthreads();
    return r;
}
__device__ __forceinline__ float blockReduceMax(float v, float* red, int t) {
    red[t] = v; __syncthreads();
    #pragma unroll
    for (int o = 128; o > 0; o >>= 1) {
        if (t < o) red[t] = fmaxf(red[t], red[t + o]);
        __syncthreads();
    }
    float r = red[0]; __syncthreads();
    return r;
}

__global__ void ma_kernel(const float* __restrict__ s, float* __restrict__ ma)
{
    int idx = blockIdx.x * blockDim.x + threadIdx.x;
    int b = idx >> 18;
    int r = idx & (SS * SS - 1);
    const float* base = s + (size_t)b * HH * SS * SS + r;
    float acc = 0.f;
    #pragma unroll
    for (int h = 0; h < HH; h++) acc += base[(size_t)h * SS * SS];
    ma[idx] = acc * 0.125f;
}

__global__ void init_acc()
{
    int t = threadIdx.x;
    if (t < BB * 5) g_acc[t] = 0.0;
    if (t < BB) g_amax[t] = 0;
}

__global__ void row_transform(const float* __restrict__ ma, float* __restrict__ tp,
                              const float* __restrict__ w1, const float* __restrict__ b1,
                              const float* __restrict__ w2, const float* __restrict__ b2)
{
    __shared__ float red[256];
    __shared__ float w1s[CC], b1s[CC], w2s[CC];
    int t = threadIdx.x;
    int row = blockIdx.x;
    int b = row >> 9;

    if (t < CC) { w1s[t] = w1[t]; b1s[t] = b1[t]; w2s[t] = w2[t]; }

    const float* mrow = ma + (size_t)row * SS;
    float m0 = mrow[t], m1 = mrow[t + 256];
    float c0 = clipf(m0, -10.f, 10.f), c1 = clipf(m1, -10.f, 10.f);
    __syncthreads();

    float mx = blockReduceMax(fmaxf(c0, c1), red, t);
    float e0 = expf(c0 - mx), e1 = expf(c1 - mx);
    float sum = blockReduceSum(e0 + e1, red, t);
    float inv = 1.f / sum;
    float p0 = e0 * inv, p1 = e1 * inv;
    float h0 = -p0 * logf(p0 + 1e-6f);
    float h1 = -p1 * logf(p1 + 1e-6f);

    float fmx = 3.f * blockReduceMax(fmaxf(h0, h1), red, t);
    float f0 = expf(3.f * h0 - fmx), f1 = expf(3.f * h1 - fmx);
    float fsum = blockReduceSum(f0 + f1, red, t);
    float finv = 1.f / fsum;
    float F0 = f0 * finv, F1 = f1 * finv;

    float b2v = b2[0];
    float sa0 = clipf(clipf(m0, -8.f, 8.f) * 0.05f, -10.f, 10.f);
    float sa1 = clipf(clipf(m1, -8.f, 8.f) * 0.05f, -10.f, 10.f);
    float a0 = 0.f, a1 = 0.f;
    #pragma unroll 8
    for (int c = 0; c < CC; c++) {
        float w = w1s[c], bb = b1s[c], w2v = w2s[c];
        float hh0 = fminf(fmaxf(sa0 * w + bb, 0.f), 5.f);
        float hh1 = fminf(fmaxf(sa1 * w + bb, 0.f), 5.f);
        a0 += hh0 * w2v;
        a1 += hh1 * w2v;
    }
    float ap0 = clipf(a0 + b2v, -5.f, 5.f);
    float ap1 = clipf(a1 + b2v, -5.f, 5.f);
    float ty0 = clipf(1.f + 0.05f * (ap0 * 50.f), 0.5f, 1.5f);
    float ty1 = clipf(1.f + 0.05f * (ap1 * 50.f), 0.5f, 1.5f);
    float sg0 = 1.f / (1.f + expf(-ty0));
    float sg1 = 1.f / (1.f + expf(-ty1));
    float tp0 = sg0 * F0, tp1 = sg1 * F1;

    tp[(size_t)row * SS + t]       = tp0;
    tp[(size_t)row * SS + t + 256] = tp1;

    float sma  = blockReduceSum(m0 + m1, red, t);
    float sma2 = blockReduceSum(m0 * m0 + m1 * m1, red, t);
    float shh  = blockReduceSum(h0 + h1, red, t);
    float stt  = blockReduceSum(tp0 + tp1, red, t);
    float st2  = blockReduceSum(tp0 * tp0 + tp1 * tp1, red, t);
    float amx  = blockReduceMax(fmaxf(fabsf(m0), fabsf(m1)), red, t);

    if (t == 0) {
        atomicAdd(&g_acc[b * 5 + 0], (double)sma);
        atomicAdd(&g_acc[b * 5 + 1], (double)sma2);
        atomicAdd(&g_acc[b * 5 + 2], (double)shh);
        atomicAdd(&g_acc[b * 5 + 3], (double)stt);
        atomicAdd(&g_acc[b * 5 + 4], (double)st2);
        atomicMax(&g_amax[b], __float_as_int(amx));
    }
}

__global__ void finalize_kernel()
{
    int b = threadIdx.x;
    if (b < BB) {
        const double N = (double)SS * (double)SS;
        double sma  = g_acc[b * 5 + 0];
        double sma2 = g_acc[b * 5 + 1];
        double sh   = g_acc[b * 5 + 2];
        double st   = g_acc[b * 5 + 3];
        double st2  = g_acc[b * 5 + 4];
        float amaxv = __int_as_float(g_amax[b]);

        float eo = sqrtf((float)sma2) + 1e-4f;
        float et = sqrtf((float)st2) + 1e-4f;
        float c  = clipf(eo / et, 0.8f, 1.2f);
        float tm = c * (float)(st / N);
        float tvar = c * c * (float)(st2 / N - (st / N) * (st / N));
        tvar = fmaxf(tvar, 0.01f);
        float ovar = (float)(sma2 / N - (sma / N) * (sma / N));
        ovar = fmaxf(ovar, 0.01f);
        float gd = clipf(sqrtf(ovar) / sqrtf(tvar), 0.8f, 1.2f);
        float ar = clipf(amaxv, 1.f, 10.f);
        float sm = clipf(0.3f / log1pf(ar), 0.1f, 0.5f);
        float ent = (float)(sh / N);
        float ne = ent / logf((float)SS);
        float rr = 0.4f * (1.f - clipf(ne, 0.f, 0.4f));
        float smgd = sm * gd;

        g_coef[b * 3 + 0] = rr * tm * (1.f - smgd);
        g_coef[b * 3 + 1] = rr * smgd * c;
        g_coef[b * 3 + 2] = rr;
    }
}

// softmax + delta, writes attn as bf16 hi/lo
__global__ void attn_softmax2(const float* __restrict__ s, const float* __restrict__ ma,
                              const float* __restrict__ tp, const float* __restrict__ tau,
                              __nv_bfloat16* __restrict__ ahi, __nv_bfloat16* __restrict__ alo)
{
    __shared__ float red[256];
    int t = threadIdx.x;
    int idx = blockIdx.x;
    int i  = idx & (SS - 1);
    int bh = idx >> 9;
    int b  = bh >> 3;

    const float* srow = s + (size_t)idx * SS;
    const float* marow = ma + ((size_t)b * SS + i) * SS;
    const float* trow  = tp + ((size_t)b * SS + i) * SS;
    float A  = g_coef[b * 3 + 0];
    float Bc = g_coef[b * 3 + 1];
    float Cc = g_coef[b * 3 + 2];
    float tauv = tau[0];

    float v0 = (srow[t]       + A + Bc * trow[t]       - Cc * marow[t])       / tauv;
    float v1 = (srow[t + 256] + A + Bc * trow[t + 256] - Cc * marow[t + 256]) / tauv;

    float mx = blockReduceMax(fmaxf(v0, v1), red, t);
    float e0 = expf(v0 - mx), e1 = expf(v1 - mx);
    float sum = blockReduceSum(e0 + e1, red, t);
    float inv = 1.f / sum;
    float p0 = e0 * inv, p1 = e1 * inv;

    __nv_bfloat16 h0 = __float2bfloat16_rn(p0);
    __nv_bfloat16 h1 = __float2bfloat16_rn(p1);
    ahi[(size_t)idx * SS + t]       = h0;
    ahi[(size_t)idx * SS + t + 256] = h1;
    alo[(size_t)idx * SS + t]       = __float2bfloat16_rn(p0 - __bfloat162float(h0));
    alo[(size_t)idx * SS + t + 256] = __float2bfloat16_rn(p1 - __bfloat162float(h1));
}

// ---------------- launch ----------------
extern "C" void kernel_launch(void* const* d_in, const int* in_sizes, int n_in,
                              void* d_out, int out_size)
{
    const float* x  = (const float*)d_in[0];
    const float* Wq = (const float*)d_in[1];
    const float* bq = (const float*)d_in[2];
    const float* Wk = (const float*)d_in[3];
    const float* bk = (const float*)d_in[4];
    const float* Wv = (const float*)d_in[5];
    const float* bv = (const float*)d_in[6];
    const float* Wo = (const float*)d_in[7];
    const float* bo = (const float*)d_in[8];
    const float* w1 = (const float*)d_in[9];
    const float* b1 = (const float*)d_in[10];
    const float* w2 = (const float*)d_in[11];
    const float* b2 = (const float*)d_in[12];
    const float* tau = (const float*)d_in[13];
    float* out = (float*)d_out;

    __nv_bfloat16 *pxhi, *pxlo, *pwthi, *pwtlo, *pqhi, *pqlo, *pkhi, *pklo, *pvthi, *pvtlo;
    __nv_bfloat16 *pahi, *palo, *pohhi, *pohlo;
    float *ps, *pma, *ptp;
    cudaGetSymbolAddress((void**)&pxhi, g_xhi);
    cudaGetSymbolAddress((void**)&pxlo, g_xlo);
    cudaGetSymbolAddress((void**)&pwthi, g_wthi);
    cudaGetSymbolAddress((void**)&pwtlo, g_wtlo);
    cudaGetSymbolAddress((void**)&pqhi, g_qhi);
    cudaGetSymbolAddress((void**)&pqlo, g_qlo);
    cudaGetSymbolAddress((void**)&pkhi, g_khi);
    cudaGetSymbolAddress((void**)&pklo, g_klo);
    cudaGetSymbolAddress((void**)&pvthi, g_vthi);
    cudaGetSymbolAddress((void**)&pvtlo, g_vtlo);
    cudaGetSymbolAddress((void**)&pahi, g_ahi);
    cudaGetSymbolAddress((void**)&palo, g_alo);
    cudaGetSymbolAddress((void**)&pohhi, g_ohhi);
    cudaGetSymbolAddress((void**)&pohlo, g_ohlo);
    cudaGetSymbolAddress((void**)&ps, g_s);
    cudaGetSymbolAddress((void**)&pma, g_ma);
    cudaGetSymbolAddress((void**)&ptp, g_tp);

    // 1) conversions
    conv_split<<<(NROW * EE) / 256, 256>>>(x, pxhi, pxlo, NROW * EE);
    conv_w<<<dim3(16, 16), dim3(32, 8)>>>(Wq, pwthi + 0 * EE * EE, pwtlo + 0 * EE * EE);
    conv_w<<<dim3(16, 16), dim3(32, 8)>>>(Wk, pwthi + 1 * EE * EE, pwtlo + 1 * EE * EE);
    conv_w<<<dim3(16, 16), dim3(32, 8)>>>(Wv, pwthi + 2 * EE * EE, pwtlo + 2 * EE * EE);
    conv_w<<<dim3(16, 16), dim3(32, 8)>>>(Wo, pwthi + 3 * EE * EE, pwtlo + 3 * EE * EE);

    // 2) fused QKV projection
    proj_qkv<<<dim3(4, 16, 3), 256>>>(pxhi, pxlo, pwthi, pwtlo, bq, bk, bv,
                                      pqhi, pqlo, pkhi, pklo, pvthi, pvtlo);

    // 3) QK^T
    qk_mma<<<dim3(4, 4, BB * HH), 256>>>(pqhi, pqlo, pkhi, pklo, ps);

    // 4) head mean + transform stats
    ma_kernel<<<(BB * SS * SS) / 256, 256>>>(ps, pma);
    init_acc<<<1, 32>>>();
    row_transform<<<NROW, 256>>>(pma, ptp, w1, b1, w2, b2);
    finalize_kernel<<<1, 32>>>();

    // 5) softmax -> attn hi/lo
    attn_softmax2<<<BB * HH * SS, 256>>>(ps, pma, ptp, tau, pahi, palo);

    // 6) attn @ V
    av_mma<<<dim3(4, BB * HH), 256>>>(pahi, palo, pvthi, pvtlo, pohhi, pohlo);

    // 7) output projection -> fp32 out
    proj_out<<<dim3(4, 16), 256>>>(pohhi, pohlo, pwthi, pwtlo, bo, out);
}